// round 1
// baseline (speedup 1.0000x reference)
#include <cuda_runtime.h>
#include <cuda_bf16.h>
#include <math.h>
#include <stdint.h>

// Problem dims (fixed)
#define BATCH 1024
#define HID   4096
#define NOUT  5

#define NH_LOG2PI (-0.9189385332046727)   // -0.5*log(2*pi)
#define PI_D 3.141592653589793238462643383279502884

// ---------------- scratch (device globals; no allocation allowed) -------------
__device__ float  g_h1[BATCH * HID];   // relu(x @ W1n.T + b1n)
__device__ float  g_h2[BATCH * HID];   // relu(h1 @ W2n.T + b2n)
__device__ double g_acc[8];            // 0:ssq(w1) 1:ssq(b1) 2:ssq(w2) 3:ssq(b2) 4:lvp3 5:lp3

// ---------------- small helpers ----------------------------------------------
__global__ void zero_acc_kernel() {
    if (threadIdx.x < 8) g_acc[threadIdx.x] = 0.0;
}

__global__ void sumsq_kernel(const float4* __restrict__ p, int n4, int slot) {
    double local = 0.0;
    for (int i = blockIdx.x * blockDim.x + threadIdx.x; i < n4; i += gridDim.x * blockDim.x) {
        float4 v = p[i];
        local += (double)v.x * v.x + (double)v.y * v.y + (double)v.z * v.z + (double)v.w * v.w;
    }
    #pragma unroll
    for (int o = 16; o; o >>= 1) local += __shfl_down_sync(0xffffffffu, local, o);
    __shared__ double s[8];
    int lane = threadIdx.x & 31, warp = threadIdx.x >> 5;
    if (lane == 0) s[warp] = local;
    __syncthreads();
    if (threadIdx.x == 0) {
        double t = 0.0;
        int nw = blockDim.x >> 5;
        for (int w = 0; w < nw; w++) t += s[w];
        atomicAdd(&g_acc[slot], t);
    }
}

// lvp3 / lp3 sums over the gaussian last layer params (20480 + 5 elems)
__global__ void rho_kernel(const float* __restrict__ w3_mu, const float* __restrict__ w3_rho,
                           const float* __restrict__ b3_mu, const float* __restrict__ b3_rho) {
    double lvp = 0.0, lp = 0.0;
    for (int i = threadIdx.x; i < NOUT * HID; i += blockDim.x) {
        double r = (double)w3_rho[i];
        lvp += NH_LOG2PI - log(log1p(exp(r)));
        double m = (double)w3_mu[i];
        lp += NH_LOG2PI - 0.5 * m * m;
    }
    if (threadIdx.x < NOUT) {
        double r = (double)b3_rho[threadIdx.x];
        lvp += NH_LOG2PI - log(log1p(exp(r)));
        double m = (double)b3_mu[threadIdx.x];
        lp += NH_LOG2PI - 0.5 * m * m;
    }
    #pragma unroll
    for (int o = 16; o; o >>= 1) {
        lvp += __shfl_down_sync(0xffffffffu, lvp, o);
        lp  += __shfl_down_sync(0xffffffffu, lp, o);
    }
    __shared__ double sv[8], sp[8];
    int lane = threadIdx.x & 31, warp = threadIdx.x >> 5;
    if (lane == 0) { sv[warp] = lvp; sp[warp] = lp; }
    __syncthreads();
    if (threadIdx.x == 0) {
        double a = 0.0, b = 0.0;
        for (int w = 0; w < 8; w++) { a += sv[w]; b += sp[w]; }
        atomicAdd(&g_acc[4], a);
        atomicAdd(&g_acc[5], b);
    }
}

__device__ __forceinline__ double log_C_vmf(double d, double kappa) {
    double s  = 0.5 * d - 1.0;
    double x  = kappa / s;
    double sq = sqrt(1.0 + x * x);
    double eta = sq + log(x) - log1p(sq);
    double logI = s * eta - 0.5 * log(2.0 * PI_D * s) - 0.5 * log(sq);
    return d * NH_LOG2PI + s * log(kappa) - logI;
}

__device__ __forceinline__ double log_surface_area(double dim) {
    double h = (dim + 1.0) * 0.5;
    float hf = (float)h;   // reference passes h through float32 into gammaln
    return log(2.0) + h * log(PI_D) - lgamma((double)hf);
}

__global__ void scalars_kernel(const float* lkw1, const float* lkb1,
                               const float* lkw2, const float* lkb2,
                               float* __restrict__ out) {
    double kw1 = exp((double)lkw1[0]) + 1e-6;
    double kb1 = exp((double)lkb1[0]) + 1e-6;
    double kw2 = exp((double)lkw2[0]) + 1e-6;
    double kb2 = exp((double)lkb2[0]) + 1e-6;
    const double dw = 4096.0 * 4096.0;   // 16777216
    const double db = 4096.0;
    // dot(mu,mu) = sumsq/sumsq = 1 exactly
    double lvp = kw1 + log_C_vmf(dw, kw1) + kb1 + log_C_vmf(db, kb1)
               + kw2 + log_C_vmf(dw, kw2) + kb2 + log_C_vmf(db, kb2)
               + g_acc[4];
    // NOTE: source bug preserved — bias prior also uses d_w, both layers
    double lp = -4.0 * log_surface_area(dw) + g_acc[5];
    out[BATCH * NOUT + 0] = (float)lvp;
    out[BATCH * NOUT + 1] = (float)lp;
}

// ---------------- bf16 tensor-core GEMM ---------------------------------------
__device__ __forceinline__ void ldsm_x4(uint32_t* r, const void* p) {
    uint32_t addr = (uint32_t)__cvta_generic_to_shared(p);
    asm volatile("ldmatrix.sync.aligned.m8n8.x4.shared.b16 {%0,%1,%2,%3}, [%4];"
                 : "=r"(r[0]), "=r"(r[1]), "=r"(r[2]), "=r"(r[3]) : "r"(addr));
}
__device__ __forceinline__ void ldsm_x2t(uint32_t* r, const void* p) {
    uint32_t addr = (uint32_t)__cvta_generic_to_shared(p);
    asm volatile("ldmatrix.sync.aligned.m8n8.x2.trans.shared.b16 {%0,%1}, [%2];"
                 : "=r"(r[0]), "=r"(r[1]) : "r"(addr));
}
__device__ __forceinline__ void mma_bf16(float* c, const uint32_t* a, const uint32_t* b) {
    asm volatile("mma.sync.aligned.m16n8k16.row.col.f32.bf16.bf16.f32 "
                 "{%0,%1,%2,%3},{%4,%5,%6,%7},{%8,%9},{%0,%1,%2,%3};"
                 : "+f"(c[0]), "+f"(c[1]), "+f"(c[2]), "+f"(c[3])
                 : "r"(a[0]), "r"(a[1]), "r"(a[2]), "r"(a[3]), "r"(b[0]), "r"(b[1]));
}

// C = relu( invW * (A @ B) + invB * bias ), B[k][n] = W[k*4096+n]
// mode 0: A = Ain (x), C = g_h1 ; mode 1: A = g_h1, C = g_h2
__global__ void __launch_bounds__(256, 2) gemm_bf16_kernel(
    const float* Ain, const float* __restrict__ W, const float* __restrict__ bias,
    int mode, int slotW, int slotB)
{
    const float* A = (mode == 0) ? Ain : g_h1;
    float* C       = (mode == 0) ? g_h1 : g_h2;

    __shared__ __align__(16) __nv_bfloat16 As[128][40];    // pad 32->40: conflict-free ldmatrix
    __shared__ __align__(16) __nv_bfloat16 Bs[32][136];    // pad 128->136

    const int tid  = threadIdx.x;
    const int lane = tid & 31, warp = tid >> 5;
    const int mBase = blockIdx.x * 128;
    const int nBase = blockIdx.y * 128;
    const int wm = (warp >> 2) * 64;   // 2 warps in M
    const int wn = (warp & 3) * 32;    // 4 warps in N

    float acc[4][4][4];
    #pragma unroll
    for (int i = 0; i < 4; i++)
        #pragma unroll
        for (int j = 0; j < 4; j++)
            #pragma unroll
            for (int k = 0; k < 4; k++) acc[i][j][k] = 0.0f;

    for (int kt = 0; kt < HID; kt += 32) {
        float4 av[4], bv[4];
        #pragma unroll
        for (int r = 0; r < 4; r++) {
            int ia = tid + r * 256;                // 1024 float4 for the 128x32 A tile
            int arow = ia >> 3, ac = ia & 7;
            av[r] = *reinterpret_cast<const float4*>(A + (size_t)(mBase + arow) * HID + kt + ac * 4);
            int ib = tid + r * 256;                // 1024 float4 for the 32x128 B tile
            int brow = ib >> 5, bc = ib & 31;
            bv[r] = *reinterpret_cast<const float4*>(W + (size_t)(kt + brow) * HID + nBase + bc * 4);
        }
        __syncthreads();   // previous compute done before overwriting smem
        #pragma unroll
        for (int r = 0; r < 4; r++) {
            int ia = tid + r * 256;
            int arow = ia >> 3, ac = (ia & 7) * 4;
            __nv_bfloat162* pa = reinterpret_cast<__nv_bfloat162*>(&As[arow][ac]);
            pa[0] = __floats2bfloat162_rn(av[r].x, av[r].y);
            pa[1] = __floats2bfloat162_rn(av[r].z, av[r].w);
            int ib = tid + r * 256;
            int brow = ib >> 5, bc = (ib & 31) * 4;
            __nv_bfloat162* pb = reinterpret_cast<__nv_bfloat162*>(&Bs[brow][bc]);
            pb[0] = __floats2bfloat162_rn(bv[r].x, bv[r].y);
            pb[1] = __floats2bfloat162_rn(bv[r].z, bv[r].w);
        }
        __syncthreads();
        #pragma unroll
        for (int ks = 0; ks < 2; ks++) {
            uint32_t af[4][4], bf[4][2];
            #pragma unroll
            for (int mi = 0; mi < 4; mi++)
                ldsm_x4(af[mi], &As[wm + mi * 16 + (lane & 15)][ks * 16 + (lane >> 4) * 8]);
            #pragma unroll
            for (int ni = 0; ni < 4; ni++)
                ldsm_x2t(bf[ni], &Bs[ks * 16 + (lane & 15)][wn + ni * 8]);
            #pragma unroll
            for (int mi = 0; mi < 4; mi++)
                #pragma unroll
                for (int ni = 0; ni < 4; ni++)
                    mma_bf16(acc[mi][ni], af[mi], bf[ni]);
        }
    }

    float invW = (float)rsqrt(g_acc[slotW]);
    float invB = (float)rsqrt(g_acc[slotB]);

    #pragma unroll
    for (int mi = 0; mi < 4; mi++) {
        #pragma unroll
        for (int ni = 0; ni < 4; ni++) {
            int row = mBase + wm + mi * 16 + (lane >> 2);
            int col = nBase + wn + ni * 8 + (lane & 3) * 2;
            float b0 = bias[col] * invB;
            float b1 = bias[col + 1] * invB;
            float v0 = fmaxf(acc[mi][ni][0] * invW + b0, 0.0f);
            float v1 = fmaxf(acc[mi][ni][1] * invW + b1, 0.0f);
            float v2 = fmaxf(acc[mi][ni][2] * invW + b0, 0.0f);
            float v3 = fmaxf(acc[mi][ni][3] * invW + b1, 0.0f);
            C[(size_t)row * HID + col]           = v0;
            C[(size_t)row * HID + col + 1]       = v1;
            C[(size_t)(row + 8) * HID + col]     = v2;
            C[(size_t)(row + 8) * HID + col + 1] = v3;
        }
    }
}

// ---------------- head: y = h2 @ w3.T + b3 ; log_softmax ----------------------
__global__ void head_kernel(const float* __restrict__ w3, const float* __restrict__ b3,
                            float* __restrict__ out) {
    int b = blockIdx.x, tid = threadIdx.x;
    const float* h = g_h2 + (size_t)b * HID;
    float p[NOUT] = {0.f, 0.f, 0.f, 0.f, 0.f};
    for (int i = tid; i < HID; i += 128) {
        float hv = h[i];
        #pragma unroll
        for (int o = 0; o < NOUT; o++) p[o] += hv * __ldg(w3 + o * HID + i);
    }
    #pragma unroll
    for (int o = 0; o < NOUT; o++)
        #pragma unroll
        for (int s = 16; s; s >>= 1) p[o] += __shfl_down_sync(0xffffffffu, p[o], s);
    __shared__ float red[4][NOUT];
    int lane = tid & 31, warp = tid >> 5;
    if (lane == 0)
        #pragma unroll
        for (int o = 0; o < NOUT; o++) red[warp][o] = p[o];
    __syncthreads();
    if (tid == 0) {
        float y[NOUT];
        #pragma unroll
        for (int o = 0; o < NOUT; o++)
            y[o] = red[0][o] + red[1][o] + red[2][o] + red[3][o] + b3[o];
        float m = y[0];
        #pragma unroll
        for (int o = 1; o < NOUT; o++) m = fmaxf(m, y[o]);
        float s = 0.f;
        #pragma unroll
        for (int o = 0; o < NOUT; o++) s += expf(y[o] - m);
        float lse = m + logf(s);
        #pragma unroll
        for (int o = 0; o < NOUT; o++) out[b * NOUT + o] = y[o] - lse;
    }
}

// ---------------- launch -------------------------------------------------------
extern "C" void kernel_launch(void* const* d_in, const int* in_sizes, int n_in,
                              void* d_out, int out_size) {
    const float* x    = (const float*)d_in[0];
    const float* w1   = (const float*)d_in[1];
    const float* lk1w = (const float*)d_in[2];
    const float* b1   = (const float*)d_in[3];
    const float* lk1b = (const float*)d_in[4];
    const float* w2   = (const float*)d_in[5];
    const float* lk2w = (const float*)d_in[6];
    const float* b2   = (const float*)d_in[7];
    const float* lk2b = (const float*)d_in[8];
    const float* w3   = (const float*)d_in[9];
    const float* w3r  = (const float*)d_in[10];
    const float* b3   = (const float*)d_in[11];
    const float* b3r  = (const float*)d_in[12];
    float* out = (float*)d_out;

    zero_acc_kernel<<<1, 32>>>();
    sumsq_kernel<<<1024, 256>>>((const float4*)w1, (HID * HID) / 4, 0);
    sumsq_kernel<<<8, 256>>>((const float4*)b1, HID / 4, 1);
    sumsq_kernel<<<1024, 256>>>((const float4*)w2, (HID * HID) / 4, 2);
    sumsq_kernel<<<8, 256>>>((const float4*)b2, HID / 4, 3);
    rho_kernel<<<1, 256>>>(w3, w3r, b3, b3r);

    dim3 grid(BATCH / 128, HID / 128);  // x = M-block (fast) so CTAs sharing W columns are adjacent
    gemm_bf16_kernel<<<grid, 256>>>(x, w1, b1, 0, 0, 1);
    gemm_bf16_kernel<<<grid, 256>>>(nullptr, w2, b2, 1, 2, 3);

    head_kernel<<<BATCH, 128>>>(w3, b3, out);
    scalars_kernel<<<1, 1>>>(lk1w, lk1b, lk2w, lk2b, out);
}

// round 3
// speedup vs baseline: 1.2679x; 1.2679x over previous
#include <cuda_runtime.h>
#include <cuda_bf16.h>
#include <math.h>
#include <stdint.h>

#define BATCH 1024
#define HID   4096
#define NOUT  5

#define NH_LOG2PI (-0.9189385332046727)
#define PI_D 3.141592653589793238462643383279502884

// ---------------- scratch --------------------------------------------------
__device__ __nv_bfloat16 g_xbf[BATCH * HID];   // bf16 x, [M,K]
__device__ __nv_bfloat16 g_w1b[HID * HID];     // bf16 W1, [K,N] (same layout as input)
__device__ __nv_bfloat16 g_w2b[HID * HID];     // bf16 W2, [K,N]
__device__ __nv_bfloat16 g_h1[BATCH * HID];    // bf16 h1 (A of GEMM2)
__device__ float         g_h2[BATCH * HID];    // fp32 h2 (head input)
__device__ double        g_acc[8];             // 0:ssq w1 1:ssq b1 2:ssq w2 3:ssq b2 4:lvp3 5:lp3

// ---------------- small kernels ---------------------------------------------
__global__ void zero_acc_kernel() { if (threadIdx.x < 8) g_acc[threadIdx.x] = 0.0; }

// streaming fp32 -> bf16 convert fused with sum-of-squares (fp32 partials, fp64 atomic)
__global__ void conv_ssq_kernel(const float4* __restrict__ src, __nv_bfloat162* __restrict__ dst,
                                int n4, int slot) {
    float ss = 0.0f;
    for (int i = blockIdx.x * blockDim.x + threadIdx.x; i < n4; i += gridDim.x * blockDim.x) {
        float4 v = src[i];
        dst[2 * i]     = __floats2bfloat162_rn(v.x, v.y);
        dst[2 * i + 1] = __floats2bfloat162_rn(v.z, v.w);
        ss += v.x * v.x + v.y * v.y + v.z * v.z + v.w * v.w;
    }
    #pragma unroll
    for (int o = 16; o; o >>= 1) ss += __shfl_down_sync(0xffffffffu, ss, o);
    __shared__ float s[8];
    int lane = threadIdx.x & 31, warp = threadIdx.x >> 5;
    if (lane == 0) s[warp] = ss;
    __syncthreads();
    if (threadIdx.x == 0) {
        double t = 0.0;
        int nw = blockDim.x >> 5;
        for (int w = 0; w < nw; w++) t += (double)s[w];
        atomicAdd(&g_acc[slot], t);
    }
}

__global__ void sumsq_kernel(const float4* __restrict__ p, int n4, int slot) {
    double local = 0.0;
    for (int i = blockIdx.x * blockDim.x + threadIdx.x; i < n4; i += gridDim.x * blockDim.x) {
        float4 v = p[i];
        local += (double)v.x * v.x + (double)v.y * v.y + (double)v.z * v.z + (double)v.w * v.w;
    }
    #pragma unroll
    for (int o = 16; o; o >>= 1) local += __shfl_down_sync(0xffffffffu, local, o);
    __shared__ double s[8];
    int lane = threadIdx.x & 31, warp = threadIdx.x >> 5;
    if (lane == 0) s[warp] = local;
    __syncthreads();
    if (threadIdx.x == 0) {
        double t = 0.0;
        int nw = blockDim.x >> 5;
        for (int w = 0; w < nw; w++) t += s[w];
        atomicAdd(&g_acc[slot], t);
    }
}

__global__ void rho_kernel(const float* __restrict__ w3_mu, const float* __restrict__ w3_rho,
                           const float* __restrict__ b3_mu, const float* __restrict__ b3_rho) {
    double lvp = 0.0, lp = 0.0;
    for (int i = threadIdx.x; i < NOUT * HID; i += blockDim.x) {
        double r = (double)w3_rho[i];
        lvp += NH_LOG2PI - log(log1p(exp(r)));
        double m = (double)w3_mu[i];
        lp += NH_LOG2PI - 0.5 * m * m;
    }
    if (threadIdx.x < NOUT) {
        double r = (double)b3_rho[threadIdx.x];
        lvp += NH_LOG2PI - log(log1p(exp(r)));
        double m = (double)b3_mu[threadIdx.x];
        lp += NH_LOG2PI - 0.5 * m * m;
    }
    #pragma unroll
    for (int o = 16; o; o >>= 1) {
        lvp += __shfl_down_sync(0xffffffffu, lvp, o);
        lp  += __shfl_down_sync(0xffffffffu, lp, o);
    }
    __shared__ double sv[8], sp[8];
    int lane = threadIdx.x & 31, warp = threadIdx.x >> 5;
    if (lane == 0) { sv[warp] = lvp; sp[warp] = lp; }
    __syncthreads();
    if (threadIdx.x == 0) {
        double a = 0.0, b = 0.0;
        for (int w = 0; w < 8; w++) { a += sv[w]; b += sp[w]; }
        atomicAdd(&g_acc[4], a);
        atomicAdd(&g_acc[5], b);
    }
}

__device__ __forceinline__ double log_C_vmf(double d, double kappa) {
    double s  = 0.5 * d - 1.0;
    double x  = kappa / s;
    double sq = sqrt(1.0 + x * x);
    double eta = sq + log(x) - log1p(sq);
    double logI = s * eta - 0.5 * log(2.0 * PI_D * s) - 0.5 * log(sq);
    return d * NH_LOG2PI + s * log(kappa) - logI;
}
__device__ __forceinline__ double log_surface_area(double dim) {
    double h = (dim + 1.0) * 0.5;
    float hf = (float)h;
    return log(2.0) + h * log(PI_D) - lgamma((double)hf);
}

__global__ void scalars_kernel(const float* lkw1, const float* lkb1,
                               const float* lkw2, const float* lkb2,
                               float* __restrict__ out) {
    double kw1 = exp((double)lkw1[0]) + 1e-6;
    double kb1 = exp((double)lkb1[0]) + 1e-6;
    double kw2 = exp((double)lkw2[0]) + 1e-6;
    double kb2 = exp((double)lkb2[0]) + 1e-6;
    const double dw = 4096.0 * 4096.0;
    const double db = 4096.0;
    double lvp = kw1 + log_C_vmf(dw, kw1) + kb1 + log_C_vmf(db, kb1)
               + kw2 + log_C_vmf(dw, kw2) + kb2 + log_C_vmf(db, kb2)
               + g_acc[4];
    double lp = -4.0 * log_surface_area(dw) + g_acc[5];   // source bug preserved
    out[BATCH * NOUT + 0] = (float)lvp;
    out[BATCH * NOUT + 1] = (float)lp;
}

// ---------------- pipelined mma.sync GEMM ------------------------------------
// C = relu(invW * (A @ W) + invB * bias).  A [M,K] bf16, W [K,N] bf16.
// CTA tile 128x256, K-chunk 64, 3-stage cp.async pipeline, 256 threads.
#define KCHUNK 64
#define NITER  (HID / KCHUNK)                 // 64
#define A_ROWB 144                            // 128B data + 16B pad (9 chunks)
#define B_ROWB 528                            // 512B data + 16B pad (33 chunks)
#define A_TILE (128 * A_ROWB)                 // 18432
#define B_TILE (KCHUNK * B_ROWB)              // 33792
#define STAGE_BYTES (A_TILE + B_TILE)         // 52224
#define GEMM_SMEM (3 * STAGE_BYTES)           // 156672

__device__ __forceinline__ void cp16(uint32_t dst, const void* src) {
    asm volatile("cp.async.cg.shared.global [%0], [%1], 16;" :: "r"(dst), "l"(src) : "memory");
}
__device__ __forceinline__ void ldsm_x4(uint32_t* r, uint32_t addr) {
    asm volatile("ldmatrix.sync.aligned.m8n8.x4.shared.b16 {%0,%1,%2,%3}, [%4];"
                 : "=r"(r[0]), "=r"(r[1]), "=r"(r[2]), "=r"(r[3]) : "r"(addr));
}
__device__ __forceinline__ void ldsm_x4t(uint32_t* r, uint32_t addr) {
    asm volatile("ldmatrix.sync.aligned.m8n8.x4.trans.shared.b16 {%0,%1,%2,%3}, [%4];"
                 : "=r"(r[0]), "=r"(r[1]), "=r"(r[2]), "=r"(r[3]) : "r"(addr));
}
__device__ __forceinline__ void mma_bf16(float* c, const uint32_t* a, const uint32_t* b) {
    asm volatile("mma.sync.aligned.m16n8k16.row.col.f32.bf16.bf16.f32 "
                 "{%0,%1,%2,%3},{%4,%5,%6,%7},{%8,%9},{%0,%1,%2,%3};"
                 : "+f"(c[0]), "+f"(c[1]), "+f"(c[2]), "+f"(c[3])
                 : "r"(a[0]), "r"(a[1]), "r"(a[2]), "r"(a[3]), "r"(b[0]), "r"(b[1]));
}

__device__ __forceinline__ void load_stage(uint32_t sA, uint32_t sB,
                                           const __nv_bfloat16* __restrict__ A,
                                           const __nv_bfloat16* __restrict__ W,
                                           int mBase, int nBase, int kt, int tid) {
    #pragma unroll
    for (int j = 0; j < 4; j++) {               // A: 1024 16B chunks
        int i = tid + j * 256;
        int r = i >> 3, c = i & 7;
        cp16(sA + r * A_ROWB + c * 16, A + (size_t)(mBase + r) * HID + kt + c * 8);
    }
    #pragma unroll
    for (int j = 0; j < 8; j++) {               // B: 2048 16B chunks
        int i = tid + j * 256;
        int r = i >> 5, c = i & 31;
        cp16(sB + r * B_ROWB + c * 16, W + (size_t)(kt + r) * HID + nBase + c * 8);
    }
    asm volatile("cp.async.commit_group;" ::: "memory");
}

__global__ void __launch_bounds__(256) gemm_mma_kernel(
    const __nv_bfloat16* __restrict__ A, const __nv_bfloat16* __restrict__ W,
    const float* __restrict__ bias, int outBf, int slotW, int slotB)
{
    extern __shared__ char smraw[];
    uint32_t smem = (uint32_t)__cvta_generic_to_shared(smraw);

    const int tid  = threadIdx.x;
    const int lane = tid & 31, warp = tid >> 5;
    const int mBase = blockIdx.x * 128;
    const int nBase = blockIdx.y * 256;
    const int wm = (warp >> 2) * 64;      // 2 warps in M
    const int wn = (warp & 3) * 64;       // 4 warps in N

    float acc[4][8][4];
    #pragma unroll
    for (int i = 0; i < 4; i++)
        #pragma unroll
        for (int j = 0; j < 8; j++)
            #pragma unroll
            for (int k = 0; k < 4; k++) acc[i][j][k] = 0.0f;

    // prologue: stages 0,1
    load_stage(smem, smem + A_TILE, A, W, mBase, nBase, 0, tid);
    load_stage(smem + STAGE_BYTES, smem + STAGE_BYTES + A_TILE, A, W, mBase, nBase, KCHUNK, tid);

    const uint32_t aLane = (uint32_t)((wm + (lane & 15)) * A_ROWB + (lane >> 4) * 16);
    const uint32_t bLane = (uint32_t)((lane & 15) * B_ROWB + (lane >> 4) * 16);

    for (int it = 0; it < NITER; ++it) {
        if (it == NITER - 1)
            asm volatile("cp.async.wait_group 0;" ::: "memory");
        else
            asm volatile("cp.async.wait_group 1;" ::: "memory");
        __syncthreads();

        if (it + 2 < NITER) {
            uint32_t s = smem + (uint32_t)((it + 2) % 3) * STAGE_BYTES;
            load_stage(s, s + A_TILE, A, W, mBase, nBase, (it + 2) * KCHUNK, tid);
        }

        uint32_t sA = smem + (uint32_t)(it % 3) * STAGE_BYTES;
        uint32_t sB = sA + A_TILE;

        #pragma unroll
        for (int ks = 0; ks < 4; ks++) {
            uint32_t af[4][4], bfr[8][2];
            #pragma unroll
            for (int mi = 0; mi < 4; mi++)
                ldsm_x4(af[mi], sA + aLane + (uint32_t)(mi * 16 * A_ROWB + ks * 32));
            #pragma unroll
            for (int ni = 0; ni < 4; ni++) {
                uint32_t r[4];
                ldsm_x4t(r, sB + bLane + (uint32_t)(ks * 16 * B_ROWB + (wn + ni * 16) * 2));
                bfr[2 * ni][0] = r[0]; bfr[2 * ni][1] = r[1];
                bfr[2 * ni + 1][0] = r[2]; bfr[2 * ni + 1][1] = r[3];
            }
            #pragma unroll
            for (int mi = 0; mi < 4; mi++)
                #pragma unroll
                for (int nf = 0; nf < 8; nf++)
                    mma_bf16(acc[mi][nf], af[mi], bfr[nf]);
        }
        __syncthreads();
    }

    // epilogue
    float invW = (float)rsqrt(g_acc[slotW]);
    float invB = (float)rsqrt(g_acc[slotB]);
    int r0 = mBase + wm + (lane >> 2);
    int c0 = nBase + wn + (lane & 3) * 2;

    #pragma unroll
    for (int mi = 0; mi < 4; mi++) {
        #pragma unroll
        for (int nf = 0; nf < 8; nf++) {
            int row = r0 + mi * 16;
            int col = c0 + nf * 8;
            float bb0 = bias[col] * invB;
            float bb1 = bias[col + 1] * invB;
            float v00 = fmaxf(acc[mi][nf][0] * invW + bb0, 0.0f);
            float v01 = fmaxf(acc[mi][nf][1] * invW + bb1, 0.0f);
            float v10 = fmaxf(acc[mi][nf][2] * invW + bb0, 0.0f);
            float v11 = fmaxf(acc[mi][nf][3] * invW + bb1, 0.0f);
            if (outBf) {
                *reinterpret_cast<__nv_bfloat162*>(g_h1 + (size_t)row * HID + col) =
                    __floats2bfloat162_rn(v00, v01);
                *reinterpret_cast<__nv_bfloat162*>(g_h1 + (size_t)(row + 8) * HID + col) =
                    __floats2bfloat162_rn(v10, v11);
            } else {
                *reinterpret_cast<float2*>(g_h2 + (size_t)row * HID + col) = make_float2(v00, v01);
                *reinterpret_cast<float2*>(g_h2 + (size_t)(row + 8) * HID + col) = make_float2(v10, v11);
            }
        }
    }
}

// ---------------- head ------------------------------------------------------
__global__ void head_kernel(const float* __restrict__ w3, const float* __restrict__ b3,
                            float* __restrict__ out) {
    int b = blockIdx.x, tid = threadIdx.x;
    const float* h = g_h2 + (size_t)b * HID;
    float p[NOUT] = {0.f, 0.f, 0.f, 0.f, 0.f};
    for (int i = tid; i < HID; i += 128) {
        float hv = h[i];
        #pragma unroll
        for (int o = 0; o < NOUT; o++) p[o] += hv * __ldg(w3 + o * HID + i);
    }
    #pragma unroll
    for (int o = 0; o < NOUT; o++)
        #pragma unroll
        for (int s = 16; s; s >>= 1) p[o] += __shfl_down_sync(0xffffffffu, p[o], s);
    __shared__ float red[4][NOUT];
    int lane = tid & 31, warp = tid >> 5;
    if (lane == 0)
        #pragma unroll
        for (int o = 0; o < NOUT; o++) red[warp][o] = p[o];
    __syncthreads();
    if (tid == 0) {
        float y[NOUT];
        #pragma unroll
        for (int o = 0; o < NOUT; o++)
            y[o] = red[0][o] + red[1][o] + red[2][o] + red[3][o] + b3[o];
        float m = y[0];
        #pragma unroll
        for (int o = 1; o < NOUT; o++) m = fmaxf(m, y[o]);
        float s = 0.f;
        #pragma unroll
        for (int o = 0; o < NOUT; o++) s += expf(y[o] - m);
        float lse = m + logf(s);
        #pragma unroll
        for (int o = 0; o < NOUT; o++) out[b * NOUT + o] = y[o] - lse;
    }
}

// ---------------- launch -----------------------------------------------------
extern "C" void kernel_launch(void* const* d_in, const int* in_sizes, int n_in,
                              void* d_out, int out_size) {
    const float* x    = (const float*)d_in[0];
    const float* w1   = (const float*)d_in[1];
    const float* lk1w = (const float*)d_in[2];
    const float* b1   = (const float*)d_in[3];
    const float* lk1b = (const float*)d_in[4];
    const float* w2   = (const float*)d_in[5];
    const float* lk2w = (const float*)d_in[6];
    const float* b2   = (const float*)d_in[7];
    const float* lk2b = (const float*)d_in[8];
    const float* w3   = (const float*)d_in[9];
    const float* w3r  = (const float*)d_in[10];
    const float* b3   = (const float*)d_in[11];
    const float* b3r  = (const float*)d_in[12];
    float* out = (float*)d_out;

    static int smem_set = 0;
    if (!smem_set) {
        cudaFuncSetAttribute(gemm_mma_kernel, cudaFuncAttributeMaxDynamicSharedMemorySize, GEMM_SMEM);
        smem_set = 1;
    }

    __nv_bfloat16 *xbf_p, *w1b_p, *w2b_p, *h1_p;
    cudaGetSymbolAddress((void**)&xbf_p, g_xbf);
    cudaGetSymbolAddress((void**)&w1b_p, g_w1b);
    cudaGetSymbolAddress((void**)&w2b_p, g_w2b);
    cudaGetSymbolAddress((void**)&h1_p, g_h1);

    zero_acc_kernel<<<1, 32>>>();
    conv_ssq_kernel<<<1184, 256>>>((const float4*)w1, (__nv_bfloat162*)w1b_p, (HID * HID) / 4, 0);
    conv_ssq_kernel<<<1184, 256>>>((const float4*)w2, (__nv_bfloat162*)w2b_p, (HID * HID) / 4, 2);
    conv_ssq_kernel<<<296, 256>>>((const float4*)x, (__nv_bfloat162*)xbf_p, (BATCH * HID) / 4, 7);
    sumsq_kernel<<<8, 256>>>((const float4*)b1, HID / 4, 1);
    sumsq_kernel<<<8, 256>>>((const float4*)b2, HID / 4, 3);
    rho_kernel<<<1, 256>>>(w3, w3r, b3, b3r);

    dim3 grid(BATCH / 128, HID / 256);   // 8 x 16 = 128 CTAs
    gemm_mma_kernel<<<grid, 256, GEMM_SMEM>>>(xbf_p, w1b_p, b1, 1, 0, 1);
    gemm_mma_kernel<<<grid, 256, GEMM_SMEM>>>(h1_p, w2b_p, b2, 0, 2, 3);

    head_kernel<<<BATCH, 128>>>(w3, b3, out);
    scalars_kernel<<<1, 1>>>(lk1w, lk1b, lk2w, lk2b, out);
}

// round 4
// speedup vs baseline: 1.2754x; 1.0060x over previous
#include <cuda_runtime.h>
#include <cuda_bf16.h>
#include <math.h>
#include <stdint.h>

#define BATCH 1024
#define HID   4096
#define NOUT  5

#define NH_LOG2PI (-0.9189385332046727)
#define PI_D 3.141592653589793238462643383279502884

// ---------------- scratch --------------------------------------------------
__device__ __nv_bfloat16 g_xbf[BATCH * HID];   // bf16 x, [M,K]
__device__ __nv_bfloat16 g_w1b[HID * HID];     // bf16 W1, [K,N]
__device__ __nv_bfloat16 g_w2b[HID * HID];     // bf16 W2, [K,N]
__device__ __nv_bfloat16 g_h1[BATCH * HID];    // bf16 h1 (A of GEMM2)
__device__ float         g_h2[BATCH * HID];    // fp32 h2 (head input)
__device__ double        g_acc[8];

// ---------------- small kernels ---------------------------------------------
__global__ void zero_acc_kernel() { if (threadIdx.x < 8) g_acc[threadIdx.x] = 0.0; }

__global__ void conv_ssq_kernel(const float4* __restrict__ src, __nv_bfloat162* __restrict__ dst,
                                int n4, int slot) {
    float ss = 0.0f;
    for (int i = blockIdx.x * blockDim.x + threadIdx.x; i < n4; i += gridDim.x * blockDim.x) {
        float4 v = src[i];
        dst[2 * i]     = __floats2bfloat162_rn(v.x, v.y);
        dst[2 * i + 1] = __floats2bfloat162_rn(v.z, v.w);
        ss += v.x * v.x + v.y * v.y + v.z * v.z + v.w * v.w;
    }
    #pragma unroll
    for (int o = 16; o; o >>= 1) ss += __shfl_down_sync(0xffffffffu, ss, o);
    __shared__ float s[8];
    int lane = threadIdx.x & 31, warp = threadIdx.x >> 5;
    if (lane == 0) s[warp] = ss;
    __syncthreads();
    if (threadIdx.x == 0) {
        double t = 0.0;
        int nw = blockDim.x >> 5;
        for (int w = 0; w < nw; w++) t += (double)s[w];
        atomicAdd(&g_acc[slot], t);
    }
}

__global__ void sumsq_kernel(const float4* __restrict__ p, int n4, int slot) {
    double local = 0.0;
    for (int i = blockIdx.x * blockDim.x + threadIdx.x; i < n4; i += gridDim.x * blockDim.x) {
        float4 v = p[i];
        local += (double)v.x * v.x + (double)v.y * v.y + (double)v.z * v.z + (double)v.w * v.w;
    }
    #pragma unroll
    for (int o = 16; o; o >>= 1) local += __shfl_down_sync(0xffffffffu, local, o);
    __shared__ double s[8];
    int lane = threadIdx.x & 31, warp = threadIdx.x >> 5;
    if (lane == 0) s[warp] = local;
    __syncthreads();
    if (threadIdx.x == 0) {
        double t = 0.0;
        int nw = blockDim.x >> 5;
        for (int w = 0; w < nw; w++) t += s[w];
        atomicAdd(&g_acc[slot], t);
    }
}

__global__ void rho_kernel(const float* __restrict__ w3_mu, const float* __restrict__ w3_rho,
                           const float* __restrict__ b3_mu, const float* __restrict__ b3_rho) {
    double lvp = 0.0, lp = 0.0;
    for (int i = threadIdx.x; i < NOUT * HID; i += blockDim.x) {
        double r = (double)w3_rho[i];
        lvp += NH_LOG2PI - log(log1p(exp(r)));
        double m = (double)w3_mu[i];
        lp += NH_LOG2PI - 0.5 * m * m;
    }
    if (threadIdx.x < NOUT) {
        double r = (double)b3_rho[threadIdx.x];
        lvp += NH_LOG2PI - log(log1p(exp(r)));
        double m = (double)b3_mu[threadIdx.x];
        lp += NH_LOG2PI - 0.5 * m * m;
    }
    #pragma unroll
    for (int o = 16; o; o >>= 1) {
        lvp += __shfl_down_sync(0xffffffffu, lvp, o);
        lp  += __shfl_down_sync(0xffffffffu, lp, o);
    }
    __shared__ double sv[8], sp[8];
    int lane = threadIdx.x & 31, warp = threadIdx.x >> 5;
    if (lane == 0) { sv[warp] = lvp; sp[warp] = lp; }
    __syncthreads();
    if (threadIdx.x == 0) {
        double a = 0.0, b = 0.0;
        for (int w = 0; w < 8; w++) { a += sv[w]; b += sp[w]; }
        atomicAdd(&g_acc[4], a);
        atomicAdd(&g_acc[5], b);
    }
}

__device__ __forceinline__ double log_C_vmf(double d, double kappa) {
    double s  = 0.5 * d - 1.0;
    double x  = kappa / s;
    double sq = sqrt(1.0 + x * x);
    double eta = sq + log(x) - log1p(sq);
    double logI = s * eta - 0.5 * log(2.0 * PI_D * s) - 0.5 * log(sq);
    return d * NH_LOG2PI + s * log(kappa) - logI;
}
__device__ __forceinline__ double log_surface_area(double dim) {
    double h = (dim + 1.0) * 0.5;
    float hf = (float)h;
    return log(2.0) + h * log(PI_D) - lgamma((double)hf);
}

__global__ void scalars_kernel(const float* lkw1, const float* lkb1,
                               const float* lkw2, const float* lkb2,
                               float* __restrict__ out) {
    double kw1 = exp((double)lkw1[0]) + 1e-6;
    double kb1 = exp((double)lkb1[0]) + 1e-6;
    double kw2 = exp((double)lkw2[0]) + 1e-6;
    double kb2 = exp((double)lkb2[0]) + 1e-6;
    const double dw = 4096.0 * 4096.0;
    const double db = 4096.0;
    double lvp = kw1 + log_C_vmf(dw, kw1) + kb1 + log_C_vmf(db, kb1)
               + kw2 + log_C_vmf(dw, kw2) + kb2 + log_C_vmf(db, kb2)
               + g_acc[4];
    double lp = -4.0 * log_surface_area(dw) + g_acc[5];   // source bug preserved
    out[BATCH * NOUT + 0] = (float)lvp;
    out[BATCH * NOUT + 1] = (float)lp;
}

// ---------------- pipelined mma.sync GEMM ------------------------------------
// CTA tile 128x256, 512 threads (16 warps, warp tile 32x64), K-chunk 64,
// 3-stage cp.async pipeline.
#define KCHUNK 64
#define NITER  (HID / KCHUNK)                 // 64
#define A_ROWB 144
#define B_ROWB 528
#define A_TILE (128 * A_ROWB)                 // 18432
#define B_TILE (KCHUNK * B_ROWB)              // 33792
#define STAGE_BYTES (A_TILE + B_TILE)         // 52224
#define GEMM_SMEM (3 * STAGE_BYTES)           // 156672

__device__ __forceinline__ void cp16(uint32_t dst, const void* src) {
    asm volatile("cp.async.cg.shared.global [%0], [%1], 16;" :: "r"(dst), "l"(src) : "memory");
}
__device__ __forceinline__ void ldsm_x4(uint32_t* r, uint32_t addr) {
    asm volatile("ldmatrix.sync.aligned.m8n8.x4.shared.b16 {%0,%1,%2,%3}, [%4];"
                 : "=r"(r[0]), "=r"(r[1]), "=r"(r[2]), "=r"(r[3]) : "r"(addr));
}
__device__ __forceinline__ void ldsm_x4t(uint32_t* r, uint32_t addr) {
    asm volatile("ldmatrix.sync.aligned.m8n8.x4.trans.shared.b16 {%0,%1,%2,%3}, [%4];"
                 : "=r"(r[0]), "=r"(r[1]), "=r"(r[2]), "=r"(r[3]) : "r"(addr));
}
__device__ __forceinline__ void mma_bf16(float* c, const uint32_t* a, const uint32_t* b) {
    asm volatile("mma.sync.aligned.m16n8k16.row.col.f32.bf16.bf16.f32 "
                 "{%0,%1,%2,%3},{%4,%5,%6,%7},{%8,%9},{%0,%1,%2,%3};"
                 : "+f"(c[0]), "+f"(c[1]), "+f"(c[2]), "+f"(c[3])
                 : "r"(a[0]), "r"(a[1]), "r"(a[2]), "r"(a[3]), "r"(b[0]), "r"(b[1]));
}

__device__ __forceinline__ void load_stage(uint32_t sA, uint32_t sB,
                                           const __nv_bfloat16* __restrict__ A,
                                           const __nv_bfloat16* __restrict__ W,
                                           int mBase, int nBase, int kt, int tid) {
    #pragma unroll
    for (int j = 0; j < 2; j++) {               // A: 1024 16B chunks / 512 thr
        int i = tid + j * 512;
        int r = i >> 3, c = i & 7;
        cp16(sA + r * A_ROWB + c * 16, A + (size_t)(mBase + r) * HID + kt + c * 8);
    }
    #pragma unroll
    for (int j = 0; j < 4; j++) {               // B: 2048 16B chunks
        int i = tid + j * 512;
        int r = i >> 5, c = i & 31;
        cp16(sB + r * B_ROWB + c * 16, W + (size_t)(kt + r) * HID + nBase + c * 8);
    }
    asm volatile("cp.async.commit_group;" ::: "memory");
}

__global__ void __launch_bounds__(512, 1) gemm_mma_kernel(
    const __nv_bfloat16* __restrict__ A, const __nv_bfloat16* __restrict__ W,
    const float* __restrict__ bias, int outBf, int slotW, int slotB)
{
    extern __shared__ char smraw[];
    uint32_t smem = (uint32_t)__cvta_generic_to_shared(smraw);

    const int tid  = threadIdx.x;
    const int lane = tid & 31, warp = tid >> 5;
    const int mBase = blockIdx.x * 128;
    const int nBase = blockIdx.y * 256;
    const int wm = (warp >> 2) * 32;      // 4 warp-rows x 32
    const int wn = (warp & 3) * 64;       // 4 warp-cols x 64

    float acc[2][8][4];
    #pragma unroll
    for (int i = 0; i < 2; i++)
        #pragma unroll
        for (int j = 0; j < 8; j++)
            #pragma unroll
            for (int k = 0; k < 4; k++) acc[i][j][k] = 0.0f;

    load_stage(smem, smem + A_TILE, A, W, mBase, nBase, 0, tid);
    load_stage(smem + STAGE_BYTES, smem + STAGE_BYTES + A_TILE, A, W, mBase, nBase, KCHUNK, tid);

    const uint32_t aLane = (uint32_t)((wm + (lane & 15)) * A_ROWB + (lane >> 4) * 16);
    const uint32_t bLane = (uint32_t)((lane & 15) * B_ROWB + (lane >> 4) * 16);

    for (int it = 0; it < NITER; ++it) {
        if (it == NITER - 1)
            asm volatile("cp.async.wait_group 0;" ::: "memory");
        else
            asm volatile("cp.async.wait_group 1;" ::: "memory");
        __syncthreads();

        if (it + 2 < NITER) {
            uint32_t s = smem + (uint32_t)((it + 2) % 3) * STAGE_BYTES;
            load_stage(s, s + A_TILE, A, W, mBase, nBase, (it + 2) * KCHUNK, tid);
        }

        uint32_t sA = smem + (uint32_t)(it % 3) * STAGE_BYTES;
        uint32_t sB = sA + A_TILE;

        #pragma unroll
        for (int ks = 0; ks < 4; ks++) {
            uint32_t af[2][4], bfr[8][2];
            #pragma unroll
            for (int mi = 0; mi < 2; mi++)
                ldsm_x4(af[mi], sA + aLane + (uint32_t)(mi * 16 * A_ROWB + ks * 32));
            #pragma unroll
            for (int ni = 0; ni < 4; ni++) {
                uint32_t r[4];
                ldsm_x4t(r, sB + bLane + (uint32_t)(ks * 16 * B_ROWB + (wn + ni * 16) * 2));
                bfr[2 * ni][0] = r[0]; bfr[2 * ni][1] = r[1];
                bfr[2 * ni + 1][0] = r[2]; bfr[2 * ni + 1][1] = r[3];
            }
            #pragma unroll
            for (int mi = 0; mi < 2; mi++)
                #pragma unroll
                for (int nf = 0; nf < 8; nf++)
                    mma_bf16(acc[mi][nf], af[mi], bfr[nf]);
        }
    }

    // epilogue
    float invW = (float)rsqrt(g_acc[slotW]);
    float invB = (float)rsqrt(g_acc[slotB]);
    int r0 = mBase + wm + (lane >> 2);
    int c0 = nBase + wn + (lane & 3) * 2;

    #pragma unroll
    for (int mi = 0; mi < 2; mi++) {
        #pragma unroll
        for (int nf = 0; nf < 8; nf++) {
            int row = r0 + mi * 16;
            int col = c0 + nf * 8;
            float bb0 = bias[col] * invB;
            float bb1 = bias[col + 1] * invB;
            float v00 = fmaxf(acc[mi][nf][0] * invW + bb0, 0.0f);
            float v01 = fmaxf(acc[mi][nf][1] * invW + bb1, 0.0f);
            float v10 = fmaxf(acc[mi][nf][2] * invW + bb0, 0.0f);
            float v11 = fmaxf(acc[mi][nf][3] * invW + bb1, 0.0f);
            if (outBf) {
                *reinterpret_cast<__nv_bfloat162*>(g_h1 + (size_t)row * HID + col) =
                    __floats2bfloat162_rn(v00, v01);
                *reinterpret_cast<__nv_bfloat162*>(g_h1 + (size_t)(row + 8) * HID + col) =
                    __floats2bfloat162_rn(v10, v11);
            } else {
                *reinterpret_cast<float2*>(g_h2 + (size_t)row * HID + col) = make_float2(v00, v01);
                *reinterpret_cast<float2*>(g_h2 + (size_t)(row + 8) * HID + col) = make_float2(v10, v11);
            }
        }
    }
}

// ---------------- head ------------------------------------------------------
__global__ void head_kernel(const float* __restrict__ w3, const float* __restrict__ b3,
                            float* __restrict__ out) {
    int b = blockIdx.x, tid = threadIdx.x;
    const float* h = g_h2 + (size_t)b * HID;
    float p[NOUT] = {0.f, 0.f, 0.f, 0.f, 0.f};
    for (int i = tid; i < HID; i += 128) {
        float hv = h[i];
        #pragma unroll
        for (int o = 0; o < NOUT; o++) p[o] += hv * __ldg(w3 + o * HID + i);
    }
    #pragma unroll
    for (int o = 0; o < NOUT; o++)
        #pragma unroll
        for (int s = 16; s; s >>= 1) p[o] += __shfl_down_sync(0xffffffffu, p[o], s);
    __shared__ float red[4][NOUT];
    int lane = tid & 31, warp = tid >> 5;
    if (lane == 0)
        #pragma unroll
        for (int o = 0; o < NOUT; o++) red[warp][o] = p[o];
    __syncthreads();
    if (tid == 0) {
        float y[NOUT];
        #pragma unroll
        for (int o = 0; o < NOUT; o++)
            y[o] = red[0][o] + red[1][o] + red[2][o] + red[3][o] + b3[o];
        float m = y[0];
        #pragma unroll
        for (int o = 1; o < NOUT; o++) m = fmaxf(m, y[o]);
        float s = 0.f;
        #pragma unroll
        for (int o = 0; o < NOUT; o++) s += expf(y[o] - m);
        float lse = m + logf(s);
        #pragma unroll
        for (int o = 0; o < NOUT; o++) out[b * NOUT + o] = y[o] - lse;
    }
}

// ---------------- launch -----------------------------------------------------
extern "C" void kernel_launch(void* const* d_in, const int* in_sizes, int n_in,
                              void* d_out, int out_size) {
    const float* x    = (const float*)d_in[0];
    const float* w1   = (const float*)d_in[1];
    const float* lk1w = (const float*)d_in[2];
    const float* b1   = (const float*)d_in[3];
    const float* lk1b = (const float*)d_in[4];
    const float* w2   = (const float*)d_in[5];
    const float* lk2w = (const float*)d_in[6];
    const float* b2   = (const float*)d_in[7];
    const float* lk2b = (const float*)d_in[8];
    const float* w3   = (const float*)d_in[9];
    const float* w3r  = (const float*)d_in[10];
    const float* b3   = (const float*)d_in[11];
    const float* b3r  = (const float*)d_in[12];
    float* out = (float*)d_out;

    static int smem_set = 0;
    if (!smem_set) {
        cudaFuncSetAttribute(gemm_mma_kernel, cudaFuncAttributeMaxDynamicSharedMemorySize, GEMM_SMEM);
        smem_set = 1;
    }

    __nv_bfloat16 *xbf_p, *w1b_p, *w2b_p, *h1_p;
    cudaGetSymbolAddress((void**)&xbf_p, g_xbf);
    cudaGetSymbolAddress((void**)&w1b_p, g_w1b);
    cudaGetSymbolAddress((void**)&w2b_p, g_w2b);
    cudaGetSymbolAddress((void**)&h1_p, g_h1);

    zero_acc_kernel<<<1, 32>>>();
    conv_ssq_kernel<<<1184, 256>>>((const float4*)w1, (__nv_bfloat162*)w1b_p, (HID * HID) / 4, 0);
    conv_ssq_kernel<<<1184, 256>>>((const float4*)w2, (__nv_bfloat162*)w2b_p, (HID * HID) / 4, 2);
    conv_ssq_kernel<<<1184, 256>>>((const float4*)x, (__nv_bfloat162*)xbf_p, (BATCH * HID) / 4, 7);
    sumsq_kernel<<<8, 256>>>((const float4*)b1, HID / 4, 1);
    sumsq_kernel<<<8, 256>>>((const float4*)b2, HID / 4, 3);
    rho_kernel<<<1, 256>>>(w3, w3r, b3, b3r);

    dim3 grid(BATCH / 128, HID / 256);   // 8 x 16 = 128 CTAs
    gemm_mma_kernel<<<grid, 512, GEMM_SMEM>>>(xbf_p, w1b_p, b1, 1, 0, 1);
    gemm_mma_kernel<<<grid, 512, GEMM_SMEM>>>(h1_p, w2b_p, b2, 0, 2, 3);

    head_kernel<<<BATCH, 128>>>(w3, b3, out);
    scalars_kernel<<<1, 1>>>(lk1w, lk1b, lk2w, lk2b, out);
}